// round 11
// baseline (speedup 1.0000x reference)
#include <cuda_runtime.h>
#include <cuda_fp16.h>
#include <cstdint>
#include <cstdio>

// Problem constants
#define Bv   32
#define Cv   64
#define Tv   12
#define Nv   1024
#define KSv  3
#define OUTv 64

#define Kdim   (KSv*Nv)        // 3072
#define Mrows  (Bv*Cv*Tv)      // 24576
#define BT     (Bv*Tv)         // 384

// ---------------- scratch ----------------
__device__ __half g_LkH[KSv * Nv * Nv];            // fp16(Lk), natural [k][n][m]
__device__ __half g_YH [(size_t)Mrows * Kdim];     // channel-mix output (fp16)
__device__ __half g_xH [(size_t)Mrows * Nv];       // fp16(x)
__device__ __half g_X1 [(size_t)Mrows * Nv];
__device__ __half g_X2 [(size_t)Mrows * Nv];
__device__ __half g_Th1[192 * 64];
__device__ __half g_Th2[192 * 64];

static __half *pLkH = nullptr, *pYH = nullptr, *pxH = nullptr;
static __half *pX1 = nullptr, *pX2 = nullptr, *pTh1 = nullptr, *pTh2 = nullptr;

// ---- helpers ----
__device__ __forceinline__ void mma_f16(float& c0, float& c1, float& c2, float& c3,
                                        uint32_t a0, uint32_t a1, uint32_t a2, uint32_t a3,
                                        uint32_t b0, uint32_t b1) {
    asm volatile(
        "mma.sync.aligned.m16n8k16.row.col.f32.f16.f16.f32 "
        "{%0,%1,%2,%3}, {%4,%5,%6,%7}, {%8,%9}, {%0,%1,%2,%3};"
        : "+f"(c0), "+f"(c1), "+f"(c2), "+f"(c3)
        : "r"(a0), "r"(a1), "r"(a2), "r"(a3), "r"(b0), "r"(b1));
}

__device__ __forceinline__ void ldsm_x4(uint32_t& r0, uint32_t& r1, uint32_t& r2, uint32_t& r3,
                                        uint32_t addr) {
    asm volatile("ldmatrix.sync.aligned.m8n8.x4.shared.b16 {%0,%1,%2,%3}, [%4];"
                 : "=r"(r0), "=r"(r1), "=r"(r2), "=r"(r3) : "r"(addr));
}
__device__ __forceinline__ void ldsm_x4_t(uint32_t& r0, uint32_t& r1, uint32_t& r2, uint32_t& r3,
                                          uint32_t addr) {
    asm volatile("ldmatrix.sync.aligned.m8n8.x4.trans.shared.b16 {%0,%1,%2,%3}, [%4];"
                 : "=r"(r0), "=r"(r1), "=r"(r2), "=r"(r3) : "r"(addr));
}

__device__ __forceinline__ void cp16(uint32_t dst_smem, const void* src) {
    asm volatile("cp.async.cg.shared.global [%0], [%1], 16;" :: "r"(dst_smem), "l"(src));
}
__device__ __forceinline__ void cp_commit() { asm volatile("cp.async.commit_group;"); }

__device__ __forceinline__ uint32_t h2bits(float a, float b) {
    __half2 h = __floats2half2_rn(a, b);
    return *reinterpret_cast<uint32_t*>(&h);
}

// XOR-scheduled shuffle within the 4-lane tg group: h[v] holds the half2 at
// half2-index j = 4v + tg of a 32-half2 (128B) row segment. After the loop,
// d[k] holds half2 j = tg*8 + k, i.e. each lane owns 32B contiguous.
__device__ __forceinline__ void seg_shuffle(const uint32_t h[8], uint32_t d[8],
                                            int gq, int tg) {
    #pragma unroll
    for (int k = 0; k < 8; k++) {
        uint32_t pub = h[2 * ((k & 3) ^ tg) + (k >> 2)];
        uint32_t got = __shfl_sync(0xffffffffu, pub, (gq << 2) | ((k & 3) ^ tg));
        d[k ^ tg] = got;
    }
}

// ---------------- prep kernels ----------------
__global__ __launch_bounds__(256) void prep_fp16(const float* __restrict__ src,
                                                 __half* __restrict__ dst)
{
    size_t i = (size_t)blockIdx.x * 1024 + threadIdx.x * 4;
    float4 v = *reinterpret_cast<const float4*>(src + i);
    *reinterpret_cast<__half2*>(dst + i)     = __floats2half2_rn(v.x, v.y);
    *reinterpret_cast<__half2*>(dst + i + 2) = __floats2half2_rn(v.z, v.w);
}

__global__ __launch_bounds__(256) void prep_thetas(const float* __restrict__ th1,
                                                   const float* __restrict__ th2,
                                                   __half* __restrict__ o1,
                                                   __half* __restrict__ o2)
{
    const float* src = blockIdx.y ? th2 : th1;
    __half*      dst = blockIdx.y ? o2  : o1;
    int idx = blockIdx.x * 256 + threadIdx.x;
    int i = idx / 192;
    int p = idx - i * 192;
    dst[p * 64 + i] = __float2half_rn(src[idx]);
}

// ---------------- kernel B: channel mix, fp16 mma, coalesced Y writes -------
#define CM_AROW 144
#define CM_BROW 272

__global__ __launch_bounds__(256, 2) void channel_mix_f16(const __half* __restrict__ X,
                                                          const __half* __restrict__ thT,
                                                          __half* __restrict__ Y)
{
    __shared__ __half As[192 * (CM_AROW/2)];
    __shared__ __half Bs[64  * (CM_BROW/2)];
    const uint32_t smA = (uint32_t)__cvta_generic_to_shared(As);
    const uint32_t smB = (uint32_t)__cvta_generic_to_shared(Bs);

    const int bt = blockIdx.x;
    const int b  = bt / Tv;
    const int t  = bt % Tv;
    const int m0 = blockIdx.y * 128;
    const int tid  = threadIdx.x;
    const int wid  = tid >> 5;
    const int lane = tid & 31;
    const int gq = lane >> 2;
    const int tg = lane & 3;
    const int wm = (wid & 3) * 48;
    const int wn = (wid >> 2) * 64;

    #pragma unroll
    for (int l = 0; l < 6; l++) {
        int slot = tid + 256 * l;
        int p = slot >> 3, q = slot & 7;
        cp16(smA + (uint32_t)(p * CM_AROW + q * 16), thT + p * 64 + q * 8);
    }
    #pragma unroll
    for (int l = 0; l < 4; l++) {
        int slot = tid + 256 * l;
        int i = slot >> 4, q = slot & 15;
        cp16(smB + (uint32_t)(i * CM_BROW + q * 16),
             X + ((size_t)(b * Cv + i) * Tv + t) * Nv + m0 + q * 8);
    }
    cp_commit();
    asm volatile("cp.async.wait_group 0;" ::: "memory");
    __syncthreads();

    float acc[3][8][4];
    #pragma unroll
    for (int a = 0; a < 3; a++)
        #pragma unroll
        for (int c = 0; c < 8; c++)
            #pragma unroll
            for (int q = 0; q < 4; q++) acc[a][c][q] = 0.f;

    const int rowA = (lane & 7) + ((lane >> 3) & 1) * 8;
    const int colA = (lane >> 4) * 16;
    const int rowB = (lane & 7) + ((lane >> 3) & 1) * 8;
    const int colB = ((lane >> 4) & 1) * 16;

    #pragma unroll
    for (int ks = 0; ks < 4; ks++) {
        uint32_t af[3][4];
        #pragma unroll
        for (int mt = 0; mt < 3; mt++)
            ldsm_x4(af[mt][0], af[mt][1], af[mt][2], af[mt][3],
                    smA + (uint32_t)((wm + 16*mt + rowA) * CM_AROW + ks * 32 + colA));
        uint32_t bf[8][2];
        #pragma unroll
        for (int ntp = 0; ntp < 4; ntp++)
            ldsm_x4_t(bf[2*ntp][0], bf[2*ntp][1], bf[2*ntp+1][0], bf[2*ntp+1][1],
                      smB + (uint32_t)((ks*16 + rowB) * CM_BROW + (wn + 16*ntp) * 2 + colB));
        #pragma unroll
        for (int mt = 0; mt < 3; mt++)
            #pragma unroll
            for (int nt = 0; nt < 8; nt++)
                mma_f16(acc[mt][nt][0], acc[mt][nt][1], acc[mt][nt][2], acc[mt][nt][3],
                        af[mt][0], af[mt][1], af[mt][2], af[mt][3],
                        bf[nt][0], bf[nt][1]);
    }

    // epilogue: coalesced scatter. Each tg-group assembles its 128B row segment.
    const int c0 = m0 + wn + tg * 16;
    #pragma unroll
    for (int mt = 0; mt < 3; mt++) {
        int p1 = wm + 16 * mt + gq;
        int p2 = p1 + 8;
        int o1 = p1 / 3, k1 = p1 - o1 * 3;
        int o2 = p2 / 3, k2 = p2 - o2 * 3;
        size_t r1 = ((size_t)(b * Cv + o1) * Tv + t) * (size_t)Kdim + (size_t)k1 * Nv;
        size_t r2 = ((size_t)(b * Cv + o2) * Tv + t) * (size_t)Kdim + (size_t)k2 * Nv;
        uint32_t h1[8], h2[8], d1[8], d2[8];
        #pragma unroll
        for (int nt = 0; nt < 8; nt++) {
            h1[nt] = h2bits(acc[mt][nt][0], acc[mt][nt][1]);
            h2[nt] = h2bits(acc[mt][nt][2], acc[mt][nt][3]);
        }
        seg_shuffle(h1, d1, gq, tg);
        seg_shuffle(h2, d2, gq, tg);
        *reinterpret_cast<uint4*>(Y + r1 + c0)     = make_uint4(d1[0], d1[1], d1[2], d1[3]);
        *reinterpret_cast<uint4*>(Y + r1 + c0 + 8) = make_uint4(d1[4], d1[5], d1[6], d1[7]);
        *reinterpret_cast<uint4*>(Y + r2 + c0)     = make_uint4(d2[0], d2[1], d2[2], d2[3]);
        *reinterpret_cast<uint4*>(Y + r2 + c0 + 8) = make_uint4(d2[4], d2[5], d2[6], d2[7]);
    }
}

// ---------------- kernel C: fp16 mma GEMM 128x128, coalesced epilogue -------
#define GBK 32
#define AROW 80
#define STAGE_A (128*AROW)
#define STAGE_BYTES (2*STAGE_A)
#define NSTAGE 4
#define GSMEM_BYTES (NSTAGE*STAGE_BYTES)   // 81920 B

__global__ __launch_bounds__(256, 2) void gemm_f16(const __half* __restrict__ A,     // [Mrows,3072]
                                                   const __half* __restrict__ Bk,    // LkH [3][1024][1024]
                                                   const float*  __restrict__ bias,  // [64]
                                                   const __half* __restrict__ resid, // [Mrows,Nv]
                                                   __half*       __restrict__ Cout)  // [Mrows,Nv]
{
    extern __shared__ char smem[];
    const uint32_t sbase = (uint32_t)__cvta_generic_to_shared(smem);

    const int bn  = blockIdx.x;     // 0..7
    const int bm  = blockIdx.y;     // 0..191
    const int tid = threadIdx.x;
    const int wid = tid >> 5;
    const int lane = tid & 31;
    const int gq  = lane >> 2;
    const int tg  = lane & 3;
    const int wm  = (wid & 3) * 32;
    const int wn  = (wid >> 2) * 64;

    const __half* Abase = A + (size_t)bm * 128 * Kdim;
    const __half* Bbase = Bk + (size_t)bn * 128 * Nv;

    auto fill_stage = [&](int s, int c) {
        const int k  = c >> 5;
        const int m0 = (c & 31) << 5;
        const __half* Asrc = Abase + (size_t)c * GBK;
        const __half* Bsrc = Bbase + ((size_t)k << 20) + m0;
        const uint32_t Asm = sbase + s * STAGE_BYTES;
        const uint32_t Bsm = Asm + STAGE_A;
        #pragma unroll
        for (int l = 0; l < 2; l++) {
            int slot = tid * 2 + l;
            int row = slot >> 2, q4 = slot & 3;
            cp16(Asm + row * AROW + q4 * 16, Asrc + (size_t)row * Kdim + q4 * 8);
        }
        #pragma unroll
        for (int l = 0; l < 2; l++) {
            int slot = tid * 2 + l;
            int row = slot >> 2, q4 = slot & 3;
            cp16(Bsm + row * AROW + q4 * 16, Bsrc + (size_t)row * Nv + q4 * 8);
        }
        cp_commit();
    };

    float acc[2][8][4];
    #pragma unroll
    for (int i = 0; i < 2; i++)
        #pragma unroll
        for (int j = 0; j < 8; j++)
            #pragma unroll
            for (int q = 0; q < 4; q++) acc[i][j][q] = 0.f;

    fill_stage(0, 0);
    fill_stage(1, 1);
    fill_stage(2, 2);

    const int rowA = (lane & 7) + ((lane >> 3) & 1) * 8;
    const int colA = (lane >> 4) * 16;
    const int rowB = (lane & 7) + ((lane >> 4) & 1) * 8;
    const int colB = ((lane >> 3) & 1) * 16;

    const int NITER = Kdim / GBK;          // 96
    for (int it = 0; it < NITER; it++) {
        asm volatile("cp.async.wait_group %0;" :: "n"(NSTAGE - 2) : "memory");
        __syncthreads();

        if (it + NSTAGE - 1 < NITER) fill_stage((it + NSTAGE - 1) & 3, it + NSTAGE - 1);
        else                         cp_commit();

        const uint32_t Acur = sbase + (it & 3) * STAGE_BYTES;
        const uint32_t Bcur = Acur + STAGE_A;

        #pragma unroll
        for (int kh = 0; kh < 2; kh++) {
            const int kb = kh * 32;
            uint32_t af[2][4];
            #pragma unroll
            for (int mt = 0; mt < 2; mt++)
                ldsm_x4(af[mt][0], af[mt][1], af[mt][2], af[mt][3],
                        Acur + (uint32_t)((wm + 16*mt + rowA) * AROW + kb + colA));
            uint32_t bf[8][2];
            #pragma unroll
            for (int ntp = 0; ntp < 4; ntp++)
                ldsm_x4(bf[2*ntp][0], bf[2*ntp][1], bf[2*ntp+1][0], bf[2*ntp+1][1],
                        Bcur + (uint32_t)((wn + 16*ntp + rowB) * AROW + kb + colB));
            #pragma unroll
            for (int mt = 0; mt < 2; mt++)
                #pragma unroll
                for (int nt = 0; nt < 8; nt++)
                    mma_f16(acc[mt][nt][0], acc[mt][nt][1], acc[mt][nt][2], acc[mt][nt][3],
                            af[mt][0], af[mt][1], af[mt][2], af[mt][3],
                            bf[nt][0], bf[nt][1]);
        }
    }

    // epilogue: shuffle to coalesced segments, then bias + resid + relu in fp32
    const int c0 = bn * 128 + wn + tg * 16;
    #pragma unroll
    for (int mt = 0; mt < 2; mt++) {
        int r1 = bm * 128 + wm + 16 * mt + gq;
        int r2 = r1 + 8;
        float bv1 = bias[(r1 / Tv) & (Cv - 1)];
        float bv2 = bias[(r2 / Tv) & (Cv - 1)];
        uint32_t h1[8], h2[8], d1[8], d2[8];
        #pragma unroll
        for (int nt = 0; nt < 8; nt++) {
            h1[nt] = h2bits(acc[mt][nt][0], acc[mt][nt][1]);
            h2[nt] = h2bits(acc[mt][nt][2], acc[mt][nt][3]);
        }
        seg_shuffle(h1, d1, gq, tg);
        seg_shuffle(h2, d2, gq, tg);

        const __half2* rp1 = reinterpret_cast<const __half2*>(resid + (size_t)r1 * Nv + c0);
        const __half2* rp2 = reinterpret_cast<const __half2*>(resid + (size_t)r2 * Nv + c0);
        uint32_t o1[8], o2[8];
        #pragma unroll
        for (int k = 0; k < 8; k++) {
            __half2 a1 = *reinterpret_cast<__half2*>(&d1[k]);
            __half2 a2 = *reinterpret_cast<__half2*>(&d2[k]);
            __half2 z1 = rp1[k];
            __half2 z2 = rp2[k];
            o1[k] = h2bits(fmaxf(__low2float(a1)  + bv1 + __low2float(z1),  0.f),
                           fmaxf(__high2float(a1) + bv1 + __high2float(z1), 0.f));
            o2[k] = h2bits(fmaxf(__low2float(a2)  + bv2 + __low2float(z2),  0.f),
                           fmaxf(__high2float(a2) + bv2 + __high2float(z2), 0.f));
        }
        *reinterpret_cast<uint4*>(Cout + (size_t)r1 * Nv + c0)     = make_uint4(o1[0], o1[1], o1[2], o1[3]);
        *reinterpret_cast<uint4*>(Cout + (size_t)r1 * Nv + c0 + 8) = make_uint4(o1[4], o1[5], o1[6], o1[7]);
        *reinterpret_cast<uint4*>(Cout + (size_t)r2 * Nv + c0)     = make_uint4(o2[0], o2[1], o2[2], o2[3]);
        *reinterpret_cast<uint4*>(Cout + (size_t)r2 * Nv + c0 + 8) = make_uint4(o2[4], o2[5], o2[6], o2[7]);
    }
}

// ---------------- kernel D: final FC (fp16 input, fp32 out) ----------------
__global__ __launch_bounds__(256) void fc_kernel(const __half* __restrict__ X2c,
                                                 const float* __restrict__ fcw,
                                                 const float* __restrict__ fcb,
                                                 float*       __restrict__ out)
{
    __shared__ float xs[Cv][65];
    __shared__ float ws[Cv][OUTv];
    __shared__ float bs[OUTv];

    int bt = blockIdx.x;
    int b  = bt / Tv;
    int t  = bt % Tv;
    int n0 = blockIdx.y * 64;
    int tid = threadIdx.x;

    for (int idx = tid; idx < Cv * OUTv; idx += 256) {
        int j = idx >> 6;
        int o = idx & 63;
        ws[o][j] = fcw[idx];
    }
    if (tid < OUTv) bs[tid] = fcb[tid];
    for (int idx = tid; idx < Cv * 64; idx += 256) {
        int o  = idx >> 6;
        int nl = idx & 63;
        xs[o][nl] = __half2float(X2c[((size_t)(b * Cv + o) * Tv + t) * Nv + n0 + nl]);
    }
    __syncthreads();

    int nl = tid & 63;
    int jg = tid >> 6;
    float acc[16];
    #pragma unroll
    for (int jj = 0; jj < 16; jj++) acc[jj] = 0.f;

    for (int o = 0; o < Cv; o++) {
        float xv = xs[o][nl];
        const float4* wrow = reinterpret_cast<const float4*>(&ws[o][jg * 16]);
        #pragma unroll
        for (int q = 0; q < 4; q++) {
            float4 w = wrow[q];
            acc[q * 4 + 0] += w.x * xv;
            acc[q * 4 + 1] += w.y * xv;
            acc[q * 4 + 2] += w.z * xv;
            acc[q * 4 + 3] += w.w * xv;
        }
    }

    size_t base = (((size_t)bt) * Nv + n0 + nl) * OUTv + jg * 16;
    #pragma unroll
    for (int q = 0; q < 4; q++) {
        float4 v;
        v.x = acc[q * 4 + 0] + bs[jg * 16 + q * 4 + 0];
        v.y = acc[q * 4 + 1] + bs[jg * 16 + q * 4 + 1];
        v.z = acc[q * 4 + 2] + bs[jg * 16 + q * 4 + 2];
        v.w = acc[q * 4 + 3] + bs[jg * 16 + q * 4 + 3];
        *reinterpret_cast<float4*>(out + base + q * 4) = v;
    }
}

// ---------------- static-init module materialization ----------------
namespace {
struct ModuleLoader {
    ModuleLoader() {
        cudaFree(0);
        cudaGetSymbolAddress((void**)&pLkH, g_LkH);
        cudaGetSymbolAddress((void**)&pYH,  g_YH);
        cudaGetSymbolAddress((void**)&pxH,  g_xH);
        cudaGetSymbolAddress((void**)&pX1,  g_X1);
        cudaGetSymbolAddress((void**)&pX2,  g_X2);
        cudaGetSymbolAddress((void**)&pTh1, g_Th1);
        cudaGetSymbolAddress((void**)&pTh2, g_Th2);
        cudaMemset(pLkH, 0, 4);
        cudaMemset(pYH,  0, 4);
        cudaMemset(pxH,  0, 4);
        cudaMemset(pX1,  0, 4);
        cudaMemset(pX2,  0, 4);
        cudaMemset(pTh1, 0, 4);
        cudaMemset(pTh2, 0, 4);
        cudaFuncSetAttribute(gemm_f16, cudaFuncAttributeMaxDynamicSharedMemorySize, GSMEM_BYTES);
        cudaDeviceSynchronize();
    }
};
ModuleLoader g_loader;
}

// ---------------- launch ----------------
extern "C" void kernel_launch(void* const* d_in, const int* in_sizes, int n_in,
                              void* d_out, int out_size)
{
    const float* x      = (const float*)d_in[0];
    const float* Lk     = (const float*)d_in[1];
    const float* theta1 = (const float*)d_in[2];
    const float* b1     = (const float*)d_in[3];
    const float* theta2 = (const float*)d_in[4];
    const float* b2     = (const float*)d_in[5];
    const float* fc_w   = (const float*)d_in[6];
    const float* fc_b   = (const float*)d_in[7];
    float* out = (float*)d_out;

    // 1) prep
    prep_fp16<<<KSv * Nv * Nv / 1024, 256>>>(Lk, pLkH);
    prep_fp16<<<(int)((size_t)Mrows * Nv / 1024), 256>>>(x, pxH);
    prep_thetas<<<dim3(48, 2), 256>>>(theta1, theta2, pTh1, pTh2);

    // 2) layer 1
    channel_mix_f16<<<dim3(BT, Nv / 128), 256>>>(pxH, pTh1, pYH);
    gemm_f16<<<dim3(8, Mrows / 128), 256, GSMEM_BYTES>>>(pYH, pLkH, b1, pxH, pX1);

    // 3) layer 2
    channel_mix_f16<<<dim3(BT, Nv / 128), 256>>>(pX1, pTh2, pYH);
    gemm_f16<<<dim3(8, Mrows / 128), 256, GSMEM_BYTES>>>(pYH, pLkH, b2, pX1, pX2);

    // 4) final FC
    fc_kernel<<<dim3(BT, Nv / 64), 256>>>(pX2, fc_w, fc_b, out);
}

// round 12
// speedup vs baseline: 1.3132x; 1.3132x over previous
#include <cuda_runtime.h>
#include <cuda_fp16.h>
#include <cstdint>
#include <cstdio>

// Problem constants
#define Bv   32
#define Cv   64
#define Tv   12
#define Nv   1024
#define KSv  3
#define OUTv 64

#define Kdim   (KSv*Nv)        // 3072
#define Mrows  (Bv*Cv*Tv)      // 24576
#define BT     (Bv*Tv)         // 384

// ---------------- scratch ----------------
__device__ __half g_LkH[KSv * Nv * Nv];            // fp16(Lk), natural [k][n][m]
__device__ __half g_YH [(size_t)Mrows * Kdim];     // channel-mix output (fp16)
__device__ __half g_xH [(size_t)Mrows * Nv];       // fp16(x)
__device__ __half g_X1 [(size_t)Mrows * Nv];
__device__ __half g_X2 [(size_t)Mrows * Nv];
__device__ __half g_Th1[192 * 64];
__device__ __half g_Th2[192 * 64];

static __half *pLkH = nullptr, *pYH = nullptr, *pxH = nullptr;
static __half *pX1 = nullptr, *pX2 = nullptr, *pTh1 = nullptr, *pTh2 = nullptr;

// ---- helpers ----
__device__ __forceinline__ void mma_f16(float& c0, float& c1, float& c2, float& c3,
                                        uint32_t a0, uint32_t a1, uint32_t a2, uint32_t a3,
                                        uint32_t b0, uint32_t b1) {
    asm volatile(
        "mma.sync.aligned.m16n8k16.row.col.f32.f16.f16.f32 "
        "{%0,%1,%2,%3}, {%4,%5,%6,%7}, {%8,%9}, {%0,%1,%2,%3};"
        : "+f"(c0), "+f"(c1), "+f"(c2), "+f"(c3)
        : "r"(a0), "r"(a1), "r"(a2), "r"(a3), "r"(b0), "r"(b1));
}

__device__ __forceinline__ void ldsm_x4(uint32_t& r0, uint32_t& r1, uint32_t& r2, uint32_t& r3,
                                        uint32_t addr) {
    asm volatile("ldmatrix.sync.aligned.m8n8.x4.shared.b16 {%0,%1,%2,%3}, [%4];"
                 : "=r"(r0), "=r"(r1), "=r"(r2), "=r"(r3) : "r"(addr));
}
__device__ __forceinline__ void ldsm_x4_t(uint32_t& r0, uint32_t& r1, uint32_t& r2, uint32_t& r3,
                                          uint32_t addr) {
    asm volatile("ldmatrix.sync.aligned.m8n8.x4.trans.shared.b16 {%0,%1,%2,%3}, [%4];"
                 : "=r"(r0), "=r"(r1), "=r"(r2), "=r"(r3) : "r"(addr));
}

__device__ __forceinline__ void cp16(uint32_t dst_smem, const void* src) {
    asm volatile("cp.async.cg.shared.global [%0], [%1], 16;" :: "r"(dst_smem), "l"(src));
}
__device__ __forceinline__ void cp_commit() { asm volatile("cp.async.commit_group;"); }

// ---------------- prep kernels ----------------
__global__ __launch_bounds__(256) void prep_fp16(const float* __restrict__ src,
                                                 __half* __restrict__ dst)
{
    size_t i = (size_t)blockIdx.x * 1024 + threadIdx.x * 4;
    float4 v = *reinterpret_cast<const float4*>(src + i);
    *reinterpret_cast<__half2*>(dst + i)     = __floats2half2_rn(v.x, v.y);
    *reinterpret_cast<__half2*>(dst + i + 2) = __floats2half2_rn(v.z, v.w);
}

__global__ __launch_bounds__(256) void prep_thetas(const float* __restrict__ th1,
                                                   const float* __restrict__ th2,
                                                   __half* __restrict__ o1,
                                                   __half* __restrict__ o2)
{
    const float* src = blockIdx.y ? th2 : th1;
    __half*      dst = blockIdx.y ? o2  : o1;
    int idx = blockIdx.x * 256 + threadIdx.x;
    int i = idx / 192;
    int p = idx - i * 192;
    dst[p * 64 + i] = __float2half_rn(src[idx]);
}

// ---------------- kernel B: channel mix, full fp16 + cp.async (R9 version) --
#define CM_AROW 144
#define CM_BROW 272

__global__ __launch_bounds__(256, 2) void channel_mix_f16(const __half* __restrict__ X,
                                                          const __half* __restrict__ thT,
                                                          __half* __restrict__ Y)
{
    __shared__ __half As[192 * (CM_AROW/2)];
    __shared__ __half Bs[64  * (CM_BROW/2)];
    const uint32_t smA = (uint32_t)__cvta_generic_to_shared(As);
    const uint32_t smB = (uint32_t)__cvta_generic_to_shared(Bs);

    const int bt = blockIdx.x;
    const int b  = bt / Tv;
    const int t  = bt % Tv;
    const int m0 = blockIdx.y * 128;
    const int tid  = threadIdx.x;
    const int wid  = tid >> 5;
    const int lane = tid & 31;
    const int gq = lane >> 2;
    const int tg = lane & 3;
    const int wm = (wid & 3) * 48;
    const int wn = (wid >> 2) * 64;

    #pragma unroll
    for (int l = 0; l < 6; l++) {
        int slot = tid + 256 * l;
        int p = slot >> 3, q = slot & 7;
        cp16(smA + (uint32_t)(p * CM_AROW + q * 16), thT + p * 64 + q * 8);
    }
    #pragma unroll
    for (int l = 0; l < 4; l++) {
        int slot = tid + 256 * l;
        int i = slot >> 4, q = slot & 15;
        cp16(smB + (uint32_t)(i * CM_BROW + q * 16),
             X + ((size_t)(b * Cv + i) * Tv + t) * Nv + m0 + q * 8);
    }
    cp_commit();
    asm volatile("cp.async.wait_group 0;" ::: "memory");
    __syncthreads();

    float acc[3][8][4];
    #pragma unroll
    for (int a = 0; a < 3; a++)
        #pragma unroll
        for (int c = 0; c < 8; c++)
            #pragma unroll
            for (int q = 0; q < 4; q++) acc[a][c][q] = 0.f;

    const int rowA = (lane & 7) + ((lane >> 3) & 1) * 8;
    const int colA = (lane >> 4) * 16;
    const int rowB = (lane & 7) + ((lane >> 3) & 1) * 8;
    const int colB = ((lane >> 4) & 1) * 16;

    #pragma unroll
    for (int ks = 0; ks < 4; ks++) {
        uint32_t af[3][4];
        #pragma unroll
        for (int mt = 0; mt < 3; mt++)
            ldsm_x4(af[mt][0], af[mt][1], af[mt][2], af[mt][3],
                    smA + (uint32_t)((wm + 16*mt + rowA) * CM_AROW + ks * 32 + colA));
        uint32_t bf[8][2];
        #pragma unroll
        for (int ntp = 0; ntp < 4; ntp++)
            ldsm_x4_t(bf[2*ntp][0], bf[2*ntp][1], bf[2*ntp+1][0], bf[2*ntp+1][1],
                      smB + (uint32_t)((ks*16 + rowB) * CM_BROW + (wn + 16*ntp) * 2 + colB));
        #pragma unroll
        for (int mt = 0; mt < 3; mt++)
            #pragma unroll
            for (int nt = 0; nt < 8; nt++)
                mma_f16(acc[mt][nt][0], acc[mt][nt][1], acc[mt][nt][2], acc[mt][nt][3],
                        af[mt][0], af[mt][1], af[mt][2], af[mt][3],
                        bf[nt][0], bf[nt][1]);
    }

    #pragma unroll
    for (int mt = 0; mt < 3; mt++) {
        int p1 = wm + 16 * mt + gq;
        int p2 = p1 + 8;
        int o1 = p1 / 3, k1 = p1 - o1 * 3;
        int o2 = p2 / 3, k2 = p2 - o2 * 3;
        size_t r1 = ((size_t)(b * Cv + o1) * Tv + t) * (size_t)Kdim + (size_t)k1 * Nv;
        size_t r2 = ((size_t)(b * Cv + o2) * Tv + t) * (size_t)Kdim + (size_t)k2 * Nv;
        #pragma unroll
        for (int nt = 0; nt < 8; nt++) {
            int c = m0 + wn + 8 * nt + 2 * tg;
            *reinterpret_cast<__half2*>(Y + r1 + c) = __floats2half2_rn(acc[mt][nt][0], acc[mt][nt][1]);
            *reinterpret_cast<__half2*>(Y + r2 + c) = __floats2half2_rn(acc[mt][nt][2], acc[mt][nt][3]);
        }
    }
}

// ---------------- kernel C: fp16 mma GEMM 128x128, GBK=64, NSTAGE=3 ---------
// C[r][n] = relu_h( sum_q Y[r][q]*B[n][q] + bias[o(r)] + resid[r][n] )
#define GBK 64
#define AROW 144                      // bytes per smem row (64 halfs + 8 pad)
#define STAGE_A (128*AROW)            // 18432 B
#define STAGE_BYTES (2*STAGE_A)       // 36864 B
#define NSTAGE 3
#define GSMEM_BYTES (NSTAGE*STAGE_BYTES)   // 110592 B

__global__ __launch_bounds__(256, 2) void gemm_f16(const __half* __restrict__ A,     // [Mrows,3072]
                                                   const __half* __restrict__ Bk,    // LkH [3][1024][1024]
                                                   const float*  __restrict__ bias,  // [64]
                                                   const __half* __restrict__ resid, // [Mrows,Nv]
                                                   __half*       __restrict__ Cout)  // [Mrows,Nv]
{
    extern __shared__ char smem[];
    const uint32_t sbase = (uint32_t)__cvta_generic_to_shared(smem);

    const int bn  = blockIdx.x;     // 0..7
    const int bm  = blockIdx.y;     // 0..191
    const int tid = threadIdx.x;
    const int wid = tid >> 5;
    const int lane = tid & 31;
    const int gq  = lane >> 2;
    const int tg  = lane & 3;
    const int wm  = (wid & 3) * 32;
    const int wn  = (wid >> 2) * 64;

    const __half* Abase = A + (size_t)bm * 128 * Kdim;
    const __half* Bbase = Bk + (size_t)bn * 128 * Nv;

    // stage index by chunk id modulo 3
    auto fill_stage = [&](int c) {
        int s = c % NSTAGE;
        const int k  = c >> 4;               // chunk covers 64 k-cols; 16 chunks per k
        const int m0 = (c & 15) << 6;
        const __half* Asrc = Abase + (size_t)c * GBK;
        const __half* Bsrc = Bbase + ((size_t)k << 20) + m0;
        const uint32_t Asm = sbase + s * STAGE_BYTES;
        const uint32_t Bsm = Asm + STAGE_A;
        #pragma unroll
        for (int l = 0; l < 4; l++) {
            int slot = tid + 256 * l;        // 0..1023
            int row = slot >> 3, q = slot & 7;
            cp16(Asm + row * AROW + q * 16, Asrc + (size_t)row * Kdim + q * 8);
        }
        #pragma unroll
        for (int l = 0; l < 4; l++) {
            int slot = tid + 256 * l;
            int row = slot >> 3, q = slot & 7;
            cp16(Bsm + row * AROW + q * 16, Bsrc + (size_t)row * Nv + q * 8);
        }
        cp_commit();
    };

    float acc[2][8][4];
    #pragma unroll
    for (int i = 0; i < 2; i++)
        #pragma unroll
        for (int j = 0; j < 8; j++)
            #pragma unroll
            for (int q = 0; q < 4; q++) acc[i][j][q] = 0.f;

    fill_stage(0);
    fill_stage(1);

    const int rowA = (lane & 7) + ((lane >> 3) & 1) * 8;
    const int colA = (lane >> 4) * 16;
    const int rowB = (lane & 7) + ((lane >> 4) & 1) * 8;
    const int colB = ((lane >> 3) & 1) * 16;

    const int NITER = Kdim / GBK;          // 48
    for (int it = 0; it < NITER; it++) {
        asm volatile("cp.async.wait_group 1;" ::: "memory");
        __syncthreads();

        if (it + 2 < NITER) fill_stage(it + 2);
        else                cp_commit();   // keep group counts aligned

        const uint32_t Acur = sbase + (it % NSTAGE) * STAGE_BYTES;
        const uint32_t Bcur = Acur + STAGE_A;

        #pragma unroll
        for (int kh = 0; kh < 4; kh++) {   // four k16 steps per 64-k chunk
            const int kb = kh * 32;
            uint32_t af[2][4];
            #pragma unroll
            for (int mt = 0; mt < 2; mt++)
                ldsm_x4(af[mt][0], af[mt][1], af[mt][2], af[mt][3],
                        Acur + (uint32_t)((wm + 16*mt + rowA) * AROW + kb + colA));
            uint32_t bf[8][2];
            #pragma unroll
            for (int ntp = 0; ntp < 4; ntp++)
                ldsm_x4(bf[2*ntp][0], bf[2*ntp][1], bf[2*ntp+1][0], bf[2*ntp+1][1],
                        Bcur + (uint32_t)((wn + 16*ntp + rowB) * AROW + kb + colB));
            #pragma unroll
            for (int mt = 0; mt < 2; mt++)
                #pragma unroll
                for (int nt = 0; nt < 8; nt++)
                    mma_f16(acc[mt][nt][0], acc[mt][nt][1], acc[mt][nt][2], acc[mt][nt][3],
                            af[mt][0], af[mt][1], af[mt][2], af[mt][3],
                            bf[nt][0], bf[nt][1]);
        }
    }

    // epilogue: bias + fp16 residual + relu (per-thread half2; sector-efficient)
    #pragma unroll
    for (int mt = 0; mt < 2; mt++) {
        int r1 = bm * 128 + wm + 16 * mt + gq;
        int r2 = r1 + 8;
        float bv1 = bias[(r1 / Tv) & (Cv - 1)];
        float bv2 = bias[(r2 / Tv) & (Cv - 1)];
        #pragma unroll
        for (int nt = 0; nt < 8; nt++) {
            int c = bn * 128 + wn + 8 * nt + 2 * tg;
            __half2 res1 = *reinterpret_cast<const __half2*>(resid + (size_t)r1 * Nv + c);
            __half2 res2 = *reinterpret_cast<const __half2*>(resid + (size_t)r2 * Nv + c);
            float v0 = fmaxf(acc[mt][nt][0] + bv1 + __low2float(res1),  0.f);
            float v1 = fmaxf(acc[mt][nt][1] + bv1 + __high2float(res1), 0.f);
            float v2 = fmaxf(acc[mt][nt][2] + bv2 + __low2float(res2),  0.f);
            float v3 = fmaxf(acc[mt][nt][3] + bv2 + __high2float(res2), 0.f);
            *reinterpret_cast<__half2*>(Cout + (size_t)r1 * Nv + c) = __floats2half2_rn(v0, v1);
            *reinterpret_cast<__half2*>(Cout + (size_t)r2 * Nv + c) = __floats2half2_rn(v2, v3);
        }
    }
}

// ---------------- kernel D: final FC (fp16 input, fp32 out) ----------------
__global__ __launch_bounds__(256) void fc_kernel(const __half* __restrict__ X2c,
                                                 const float* __restrict__ fcw,
                                                 const float* __restrict__ fcb,
                                                 float*       __restrict__ out)
{
    __shared__ float xs[Cv][65];
    __shared__ float ws[Cv][OUTv];
    __shared__ float bs[OUTv];

    int bt = blockIdx.x;
    int b  = bt / Tv;
    int t  = bt % Tv;
    int n0 = blockIdx.y * 64;
    int tid = threadIdx.x;

    for (int idx = tid; idx < Cv * OUTv; idx += 256) {
        int j = idx >> 6;
        int o = idx & 63;
        ws[o][j] = fcw[idx];
    }
    if (tid < OUTv) bs[tid] = fcb[tid];
    for (int idx = tid; idx < Cv * 64; idx += 256) {
        int o  = idx >> 6;
        int nl = idx & 63;
        xs[o][nl] = __half2float(X2c[((size_t)(b * Cv + o) * Tv + t) * Nv + n0 + nl]);
    }
    __syncthreads();

    int nl = tid & 63;
    int jg = tid >> 6;
    float acc[16];
    #pragma unroll
    for (int jj = 0; jj < 16; jj++) acc[jj] = 0.f;

    for (int o = 0; o < Cv; o++) {
        float xv = xs[o][nl];
        const float4* wrow = reinterpret_cast<const float4*>(&ws[o][jg * 16]);
        #pragma unroll
        for (int q = 0; q < 4; q++) {
            float4 w = wrow[q];
            acc[q * 4 + 0] += w.x * xv;
            acc[q * 4 + 1] += w.y * xv;
            acc[q * 4 + 2] += w.z * xv;
            acc[q * 4 + 3] += w.w * xv;
        }
    }

    size_t base = (((size_t)bt) * Nv + n0 + nl) * OUTv + jg * 16;
    #pragma unroll
    for (int q = 0; q < 4; q++) {
        float4 v;
        v.x = acc[q * 4 + 0] + bs[jg * 16 + q * 4 + 0];
        v.y = acc[q * 4 + 1] + bs[jg * 16 + q * 4 + 1];
        v.z = acc[q * 4 + 2] + bs[jg * 16 + q * 4 + 2];
        v.w = acc[q * 4 + 3] + bs[jg * 16 + q * 4 + 3];
        *reinterpret_cast<float4*>(out + base + q * 4) = v;
    }
}

// ---------------- static-init module materialization ----------------
namespace {
struct ModuleLoader {
    ModuleLoader() {
        cudaFree(0);
        cudaGetSymbolAddress((void**)&pLkH, g_LkH);
        cudaGetSymbolAddress((void**)&pYH,  g_YH);
        cudaGetSymbolAddress((void**)&pxH,  g_xH);
        cudaGetSymbolAddress((void**)&pX1,  g_X1);
        cudaGetSymbolAddress((void**)&pX2,  g_X2);
        cudaGetSymbolAddress((void**)&pTh1, g_Th1);
        cudaGetSymbolAddress((void**)&pTh2, g_Th2);
        cudaMemset(pLkH, 0, 4);
        cudaMemset(pYH,  0, 4);
        cudaMemset(pxH,  0, 4);
        cudaMemset(pX1,  0, 4);
        cudaMemset(pX2,  0, 4);
        cudaMemset(pTh1, 0, 4);
        cudaMemset(pTh2, 0, 4);
        cudaFuncSetAttribute(gemm_f16, cudaFuncAttributeMaxDynamicSharedMemorySize, GSMEM_BYTES);
        cudaDeviceSynchronize();
    }
};
ModuleLoader g_loader;
}

// ---------------- launch ----------------
extern "C" void kernel_launch(void* const* d_in, const int* in_sizes, int n_in,
                              void* d_out, int out_size)
{
    const float* x      = (const float*)d_in[0];
    const float* Lk     = (const float*)d_in[1];
    const float* theta1 = (const float*)d_in[2];
    const float* b1     = (const float*)d_in[3];
    const float* theta2 = (const float*)d_in[4];
    const float* b2     = (const float*)d_in[5];
    const float* fc_w   = (const float*)d_in[6];
    const float* fc_b   = (const float*)d_in[7];
    float* out = (float*)d_out;

    // 1) prep (all parallel, tiny)
    prep_fp16<<<KSv * Nv * Nv / 1024, 256>>>(Lk, pLkH);
    prep_fp16<<<(int)((size_t)Mrows * Nv / 1024), 256>>>(x, pxH);
    prep_thetas<<<dim3(48, 2), 256>>>(theta1, theta2, pTh1, pTh2);

    // 2) layer 1
    channel_mix_f16<<<dim3(BT, Nv / 128), 256>>>(pxH, pTh1, pYH);
    gemm_f16<<<dim3(8, Mrows / 128), 256, GSMEM_BYTES>>>(pYH, pLkH, b1, pxH, pX1);

    // 3) layer 2
    channel_mix_f16<<<dim3(BT, Nv / 128), 256>>>(pX1, pTh2, pYH);
    gemm_f16<<<dim3(8, Mrows / 128), 256, GSMEM_BYTES>>>(pYH, pLkH, b2, pX1, pX2);

    // 4) final FC
    fc_kernel<<<dim3(BT, Nv / 64), 256>>>(pX2, fc_w, fc_b, out);
}

// round 13
// speedup vs baseline: 1.3175x; 1.0032x over previous
#include <cuda_runtime.h>
#include <cuda_fp16.h>
#include <cstdint>
#include <cstdio>

// Problem constants
#define Bv   32
#define Cv   64
#define Tv   12
#define Nv   1024
#define KSv  3
#define OUTv 64

#define Kdim   (KSv*Nv)        // 3072
#define Mrows  (Bv*Cv*Tv)      // 24576
#define BT     (Bv*Tv)         // 384

// ---------------- scratch ----------------
__device__ __half g_LkH[KSv * Nv * Nv];            // fp16(Lk), natural [k][n][m]
__device__ __half g_YH [(size_t)Mrows * Kdim];     // channel-mix output (fp16)
__device__ __half g_X1 [(size_t)Mrows * Nv];
__device__ __half g_X2 [(size_t)Mrows * Nv];
__device__ __half g_Th1[192 * 64];
__device__ __half g_Th2[192 * 64];

static __half *pLkH = nullptr, *pYH = nullptr;
static __half *pX1 = nullptr, *pX2 = nullptr, *pTh1 = nullptr, *pTh2 = nullptr;

// ---- helpers ----
__device__ __forceinline__ void mma_f16(float& c0, float& c1, float& c2, float& c3,
                                        uint32_t a0, uint32_t a1, uint32_t a2, uint32_t a3,
                                        uint32_t b0, uint32_t b1) {
    asm volatile(
        "mma.sync.aligned.m16n8k16.row.col.f32.f16.f16.f32 "
        "{%0,%1,%2,%3}, {%4,%5,%6,%7}, {%8,%9}, {%0,%1,%2,%3};"
        : "+f"(c0), "+f"(c1), "+f"(c2), "+f"(c3)
        : "r"(a0), "r"(a1), "r"(a2), "r"(a3), "r"(b0), "r"(b1));
}

__device__ __forceinline__ void ldsm_x4(uint32_t& r0, uint32_t& r1, uint32_t& r2, uint32_t& r3,
                                        uint32_t addr) {
    asm volatile("ldmatrix.sync.aligned.m8n8.x4.shared.b16 {%0,%1,%2,%3}, [%4];"
                 : "=r"(r0), "=r"(r1), "=r"(r2), "=r"(r3) : "r"(addr));
}
__device__ __forceinline__ void ldsm_x4_t(uint32_t& r0, uint32_t& r1, uint32_t& r2, uint32_t& r3,
                                          uint32_t addr) {
    asm volatile("ldmatrix.sync.aligned.m8n8.x4.trans.shared.b16 {%0,%1,%2,%3}, [%4];"
                 : "=r"(r0), "=r"(r1), "=r"(r2), "=r"(r3) : "r"(addr));
}

__device__ __forceinline__ void cp16(uint32_t dst_smem, const void* src) {
    asm volatile("cp.async.cg.shared.global [%0], [%1], 16;" :: "r"(dst_smem), "l"(src));
}
__device__ __forceinline__ void cp_commit() { asm volatile("cp.async.commit_group;"); }

// ---------------- prep: Lk convert + both theta transposes, ONE launch ------
__global__ __launch_bounds__(256) void prep_all(const float* __restrict__ Lk,
                                                const float* __restrict__ th1,
                                                const float* __restrict__ th2,
                                                __half* __restrict__ LkH,
                                                __half* __restrict__ o1,
                                                __half* __restrict__ o2)
{
    int bid = blockIdx.x;
    if (bid < 3072) {
        size_t i = (size_t)bid * 1024 + threadIdx.x * 4;
        float4 v = *reinterpret_cast<const float4*>(Lk + i);
        *reinterpret_cast<__half2*>(LkH + i)     = __floats2half2_rn(v.x, v.y);
        *reinterpret_cast<__half2*>(LkH + i + 2) = __floats2half2_rn(v.z, v.w);
    } else {
        int b2 = bid - 3072;                 // 0..95
        const float* src = (b2 >= 48) ? th2 : th1;
        __half*      dst = (b2 >= 48) ? o2  : o1;
        int idx = (b2 % 48) * 256 + threadIdx.x;
        int i = idx / 192;
        int p = idx - i * 192;
        dst[p * 64 + i] = __float2half_rn(src[idx]);
    }
}

// ---------------- kernel B: channel mix, fp16 mma; XF32 selects input dtype -
#define CM_AROW 144
#define CM_BROW 272

template <bool XF32>
__global__ __launch_bounds__(256, 2) void channel_mix_f16(const void* __restrict__ Xv,
                                                          const __half* __restrict__ thT,
                                                          __half* __restrict__ Y)
{
    __shared__ __half As[192 * (CM_AROW/2)];
    __shared__ __half Bs[64  * (CM_BROW/2)];
    const uint32_t smA = (uint32_t)__cvta_generic_to_shared(As);
    const uint32_t smB = (uint32_t)__cvta_generic_to_shared(Bs);

    const int bt = blockIdx.x;
    const int b  = bt / Tv;
    const int t  = bt % Tv;
    const int m0 = blockIdx.y * 128;
    const int tid  = threadIdx.x;
    const int wid  = tid >> 5;
    const int lane = tid & 31;
    const int gq = lane >> 2;
    const int tg = lane & 3;
    const int wm = (wid & 3) * 48;
    const int wn = (wid >> 2) * 64;

    // theta tile via cp.async
    #pragma unroll
    for (int l = 0; l < 6; l++) {
        int slot = tid + 256 * l;
        int p = slot >> 3, q = slot & 7;
        cp16(smA + (uint32_t)(p * CM_AROW + q * 16), thT + p * 64 + q * 8);
    }
    // x tile
    if (XF32) {
        const float* X = (const float*)Xv;
        #pragma unroll
        for (int l = 0; l < 8; l++) {
            int f  = tid + 256 * l;           // 2048 float4 slots
            int i  = f >> 5;
            int mv = (f & 31) * 4;
            float4 v = *reinterpret_cast<const float4*>(
                X + ((size_t)(b * Cv + i) * Tv + t) * Nv + m0 + mv);
            __half* dst = &Bs[i * (CM_BROW/2) + mv];
            *reinterpret_cast<__half2*>(dst)     = __floats2half2_rn(v.x, v.y);
            *reinterpret_cast<__half2*>(dst + 2) = __floats2half2_rn(v.z, v.w);
        }
    } else {
        const __half* X = (const __half*)Xv;
        #pragma unroll
        for (int l = 0; l < 4; l++) {
            int slot = tid + 256 * l;
            int i = slot >> 4, q = slot & 15;
            cp16(smB + (uint32_t)(i * CM_BROW + q * 16),
                 X + ((size_t)(b * Cv + i) * Tv + t) * Nv + m0 + q * 8);
        }
    }
    cp_commit();
    asm volatile("cp.async.wait_group 0;" ::: "memory");
    __syncthreads();

    float acc[3][8][4];
    #pragma unroll
    for (int a = 0; a < 3; a++)
        #pragma unroll
        for (int c = 0; c < 8; c++)
            #pragma unroll
            for (int q = 0; q < 4; q++) acc[a][c][q] = 0.f;

    const int rowA = (lane & 7) + ((lane >> 3) & 1) * 8;
    const int colA = (lane >> 4) * 16;
    const int rowB = (lane & 7) + ((lane >> 3) & 1) * 8;
    const int colB = ((lane >> 4) & 1) * 16;

    #pragma unroll
    for (int ks = 0; ks < 4; ks++) {
        uint32_t af[3][4];
        #pragma unroll
        for (int mt = 0; mt < 3; mt++)
            ldsm_x4(af[mt][0], af[mt][1], af[mt][2], af[mt][3],
                    smA + (uint32_t)((wm + 16*mt + rowA) * CM_AROW + ks * 32 + colA));
        uint32_t bf[8][2];
        #pragma unroll
        for (int ntp = 0; ntp < 4; ntp++)
            ldsm_x4_t(bf[2*ntp][0], bf[2*ntp][1], bf[2*ntp+1][0], bf[2*ntp+1][1],
                      smB + (uint32_t)((ks*16 + rowB) * CM_BROW + (wn + 16*ntp) * 2 + colB));
        #pragma unroll
        for (int mt = 0; mt < 3; mt++)
            #pragma unroll
            for (int nt = 0; nt < 8; nt++)
                mma_f16(acc[mt][nt][0], acc[mt][nt][1], acc[mt][nt][2], acc[mt][nt][3],
                        af[mt][0], af[mt][1], af[mt][2], af[mt][3],
                        bf[nt][0], bf[nt][1]);
    }

    #pragma unroll
    for (int mt = 0; mt < 3; mt++) {
        int p1 = wm + 16 * mt + gq;
        int p2 = p1 + 8;
        int o1 = p1 / 3, k1 = p1 - o1 * 3;
        int o2 = p2 / 3, k2 = p2 - o2 * 3;
        size_t r1 = ((size_t)(b * Cv + o1) * Tv + t) * (size_t)Kdim + (size_t)k1 * Nv;
        size_t r2 = ((size_t)(b * Cv + o2) * Tv + t) * (size_t)Kdim + (size_t)k2 * Nv;
        #pragma unroll
        for (int nt = 0; nt < 8; nt++) {
            int c = m0 + wn + 8 * nt + 2 * tg;
            *reinterpret_cast<__half2*>(Y + r1 + c) = __floats2half2_rn(acc[mt][nt][0], acc[mt][nt][1]);
            *reinterpret_cast<__half2*>(Y + r2 + c) = __floats2half2_rn(acc[mt][nt][2], acc[mt][nt][3]);
        }
    }
}

// ---------------- kernel C: fp16 mma GEMM, tile 96x128, GBK=64, NSTAGE=3 ----
// C[r][n] = relu_h( mm + bias[o(r)] + resid[r][n] ), RF32 selects resid dtype.
#define GBM 96
#define GBK 64
#define AROW 144                       // 64 halfs + 8 pad
#define STAGE_ROWS (GBM + 128)         // 224 rows: A then B
#define STAGE_BYTES (STAGE_ROWS * AROW)  // 32256
#define NSTAGE 3
#define GSMEM_BYTES (NSTAGE*STAGE_BYTES)   // 96768

template <bool RF32>
__global__ __launch_bounds__(256, 2) void gemm_f16(const __half* __restrict__ A,     // [Mrows,3072]
                                                   const __half* __restrict__ Bk,    // LkH [3][1024][1024]
                                                   const float*  __restrict__ bias,  // [64]
                                                   const void*   __restrict__ residv,// [Mrows,Nv]
                                                   __half*       __restrict__ Cout)  // [Mrows,Nv]
{
    extern __shared__ char smem[];
    const uint32_t sbase = (uint32_t)__cvta_generic_to_shared(smem);

    const int bn  = blockIdx.x;     // 0..7
    const int bm  = blockIdx.y;     // 0..255
    const int tid = threadIdx.x;
    const int wid = tid >> 5;
    const int lane = tid & 31;
    const int gq  = lane >> 2;
    const int tg  = lane & 3;
    const int wm  = (wid & 1) * 48;     // 2 warps in m
    const int wn  = (wid >> 1) * 32;    // 4 warps in n

    const __half* Abase = A + (size_t)bm * GBM * Kdim;
    const __half* Bbase = Bk + (size_t)bn * 128 * Nv;

    auto fill_stage = [&](int c) {
        int s = c % NSTAGE;
        const int k  = c >> 4;
        const int m0 = (c & 15) << 6;
        const __half* Asrc = Abase + (size_t)c * GBK;
        const __half* Bsrc = Bbase + ((size_t)k << 20) + m0;
        const uint32_t Asm = sbase + s * STAGE_BYTES;
        const uint32_t Bsm = Asm + GBM * AROW;
        #pragma unroll
        for (int l = 0; l < 7; l++) {
            int slot = tid + 256 * l;          // 0..1791
            int row = slot >> 3, q = slot & 7;
            if (row < GBM)
                cp16(Asm + row * AROW + q * 16, Asrc + (size_t)row * Kdim + q * 8);
            else
                cp16(Bsm + (row - GBM) * AROW + q * 16, Bsrc + (size_t)(row - GBM) * Nv + q * 8);
        }
        cp_commit();
    };

    float acc[3][4][4];
    #pragma unroll
    for (int i = 0; i < 3; i++)
        #pragma unroll
        for (int j = 0; j < 4; j++)
            #pragma unroll
            for (int q = 0; q < 4; q++) acc[i][j][q] = 0.f;

    fill_stage(0);
    fill_stage(1);

    const int rowA = (lane & 7) + ((lane >> 3) & 1) * 8;
    const int colA = (lane >> 4) * 16;
    const int rowB = (lane & 7) + ((lane >> 4) & 1) * 8;
    const int colB = ((lane >> 3) & 1) * 16;

    const int NITER = Kdim / GBK;          // 48
    for (int it = 0; it < NITER; it++) {
        asm volatile("cp.async.wait_group 1;" ::: "memory");
        __syncthreads();

        if (it + 2 < NITER) fill_stage(it + 2);
        else                cp_commit();

        const uint32_t Acur = sbase + (it % NSTAGE) * STAGE_BYTES;
        const uint32_t Bcur = Acur + GBM * AROW;

        #pragma unroll
        for (int kh = 0; kh < 4; kh++) {
            const int kb = kh * 32;
            uint32_t af[3][4];
            #pragma unroll
            for (int mt = 0; mt < 3; mt++)
                ldsm_x4(af[mt][0], af[mt][1], af[mt][2], af[mt][3],
                        Acur + (uint32_t)((wm + 16*mt + rowA) * AROW + kb + colA));
            uint32_t bf[4][2];
            #pragma unroll
            for (int ntp = 0; ntp < 2; ntp++)
                ldsm_x4(bf[2*ntp][0], bf[2*ntp][1], bf[2*ntp+1][0], bf[2*ntp+1][1],
                        Bcur + (uint32_t)((wn + 16*ntp + rowB) * AROW + kb + colB));
            #pragma unroll
            for (int mt = 0; mt < 3; mt++)
                #pragma unroll
                for (int nt = 0; nt < 4; nt++)
                    mma_f16(acc[mt][nt][0], acc[mt][nt][1], acc[mt][nt][2], acc[mt][nt][3],
                            af[mt][0], af[mt][1], af[mt][2], af[mt][3],
                            bf[nt][0], bf[nt][1]);
        }
    }

    // epilogue
    #pragma unroll
    for (int mt = 0; mt < 3; mt++) {
        int r1 = bm * GBM + wm + 16 * mt + gq;
        int r2 = r1 + 8;
        float bv1 = bias[(r1 / Tv) & (Cv - 1)];
        float bv2 = bias[(r2 / Tv) & (Cv - 1)];
        #pragma unroll
        for (int nt = 0; nt < 4; nt++) {
            int c = bn * 128 + wn + 8 * nt + 2 * tg;
            float z10, z11, z20, z21;
            if (RF32) {
                const float* rp = (const float*)residv;
                float2 a = *reinterpret_cast<const float2*>(rp + (size_t)r1 * Nv + c);
                float2 b2_ = *reinterpret_cast<const float2*>(rp + (size_t)r2 * Nv + c);
                z10 = a.x;  z11 = a.y;  z20 = b2_.x; z21 = b2_.y;
            } else {
                const __half* rp = (const __half*)residv;
                __half2 a = *reinterpret_cast<const __half2*>(rp + (size_t)r1 * Nv + c);
                __half2 b2_ = *reinterpret_cast<const __half2*>(rp + (size_t)r2 * Nv + c);
                z10 = __low2float(a);  z11 = __high2float(a);
                z20 = __low2float(b2_); z21 = __high2float(b2_);
            }
            float v0 = fmaxf(acc[mt][nt][0] + bv1 + z10, 0.f);
            float v1 = fmaxf(acc[mt][nt][1] + bv1 + z11, 0.f);
            float v2 = fmaxf(acc[mt][nt][2] + bv2 + z20, 0.f);
            float v3 = fmaxf(acc[mt][nt][3] + bv2 + z21, 0.f);
            *reinterpret_cast<__half2*>(Cout + (size_t)r1 * Nv + c) = __floats2half2_rn(v0, v1);
            *reinterpret_cast<__half2*>(Cout + (size_t)r2 * Nv + c) = __floats2half2_rn(v2, v3);
        }
    }
}

// ---------------- kernel D: final FC (fp16 input, fp32 out) ----------------
__global__ __launch_bounds__(256) void fc_kernel(const __half* __restrict__ X2c,
                                                 const float* __restrict__ fcw,
                                                 const float* __restrict__ fcb,
                                                 float*       __restrict__ out)
{
    __shared__ float xs[Cv][65];
    __shared__ float ws[Cv][OUTv];
    __shared__ float bs[OUTv];

    int bt = blockIdx.x;
    int b  = bt / Tv;
    int t  = bt % Tv;
    int n0 = blockIdx.y * 64;
    int tid = threadIdx.x;

    for (int idx = tid; idx < Cv * OUTv; idx += 256) {
        int j = idx >> 6;
        int o = idx & 63;
        ws[o][j] = fcw[idx];
    }
    if (tid < OUTv) bs[tid] = fcb[tid];
    for (int idx = tid; idx < Cv * 32; idx += 256) {
        int o  = idx >> 5;
        int nl = (idx & 31) * 2;
        __half2 h = *reinterpret_cast<const __half2*>(
            X2c + ((size_t)(b * Cv + o) * Tv + t) * Nv + n0 + nl);
        xs[o][nl]     = __low2float(h);
        xs[o][nl + 1] = __high2float(h);
    }
    __syncthreads();

    int nl = tid & 63;
    int jg = tid >> 6;
    float acc[16];
    #pragma unroll
    for (int jj = 0; jj < 16; jj++) acc[jj] = 0.f;

    for (int o = 0; o < Cv; o++) {
        float xv = xs[o][nl];
        const float4* wrow = reinterpret_cast<const float4*>(&ws[o][jg * 16]);
        #pragma unroll
        for (int q = 0; q < 4; q++) {
            float4 w = wrow[q];
            acc[q * 4 + 0] += w.x * xv;
            acc[q * 4 + 1] += w.y * xv;
            acc[q * 4 + 2] += w.z * xv;
            acc[q * 4 + 3] += w.w * xv;
        }
    }

    size_t base = (((size_t)bt) * Nv + n0 + nl) * OUTv + jg * 16;
    #pragma unroll
    for (int q = 0; q < 4; q++) {
        float4 v;
        v.x = acc[q * 4 + 0] + bs[jg * 16 + q * 4 + 0];
        v.y = acc[q * 4 + 1] + bs[jg * 16 + q * 4 + 1];
        v.z = acc[q * 4 + 2] + bs[jg * 16 + q * 4 + 2];
        v.w = acc[q * 4 + 3] + bs[jg * 16 + q * 4 + 3];
        *reinterpret_cast<float4*>(out + base + q * 4) = v;
    }
}

// ---------------- static-init module materialization ----------------
namespace {
struct ModuleLoader {
    ModuleLoader() {
        cudaFree(0);
        cudaGetSymbolAddress((void**)&pLkH, g_LkH);
        cudaGetSymbolAddress((void**)&pYH,  g_YH);
        cudaGetSymbolAddress((void**)&pX1,  g_X1);
        cudaGetSymbolAddress((void**)&pX2,  g_X2);
        cudaGetSymbolAddress((void**)&pTh1, g_Th1);
        cudaGetSymbolAddress((void**)&pTh2, g_Th2);
        cudaMemset(pLkH, 0, 4);
        cudaMemset(pYH,  0, 4);
        cudaMemset(pX1,  0, 4);
        cudaMemset(pX2,  0, 4);
        cudaMemset(pTh1, 0, 4);
        cudaMemset(pTh2, 0, 4);
        cudaFuncSetAttribute(gemm_f16<true>,  cudaFuncAttributeMaxDynamicSharedMemorySize, GSMEM_BYTES);
        cudaFuncSetAttribute(gemm_f16<false>, cudaFuncAttributeMaxDynamicSharedMemorySize, GSMEM_BYTES);
        cudaDeviceSynchronize();
    }
};
ModuleLoader g_loader;
}

// ---------------- launch ----------------
extern "C" void kernel_launch(void* const* d_in, const int* in_sizes, int n_in,
                              void* d_out, int out_size)
{
    const float* x      = (const float*)d_in[0];
    const float* Lk     = (const float*)d_in[1];
    const float* theta1 = (const float*)d_in[2];
    const float* b1     = (const float*)d_in[3];
    const float* theta2 = (const float*)d_in[4];
    const float* b2     = (const float*)d_in[5];
    const float* fc_w   = (const float*)d_in[6];
    const float* fc_b   = (const float*)d_in[7];
    float* out = (float*)d_out;

    // 1) prep: Lk fp16 + both theta transposes, one launch
    prep_all<<<3072 + 96, 256>>>(Lk, theta1, theta2, pLkH, pTh1, pTh2);

    // 2) layer 1 (x consumed as fp32 directly)
    channel_mix_f16<true><<<dim3(BT, Nv / 128), 256>>>(x, pTh1, pYH);
    gemm_f16<true><<<dim3(8, Mrows / GBM), 256, GSMEM_BYTES>>>(pYH, pLkH, b1, x, pX1);

    // 3) layer 2
    channel_mix_f16<false><<<dim3(BT, Nv / 128), 256>>>(pX1, pTh2, pYH);
    gemm_f16<false><<<dim3(8, Mrows / GBM), 256, GSMEM_BYTES>>>(pYH, pLkH, b2, pX1, pX2);

    // 4) final FC
    fc_kernel<<<dim3(BT, Nv / 64), 256>>>(pX2, fc_w, fc_b, out);
}

// round 14
// speedup vs baseline: 1.5310x; 1.1621x over previous
#include <cuda_runtime.h>
#include <cuda_fp16.h>
#include <cstdint>
#include <cstdio>

// Problem constants
#define Bv   32
#define Cv   64
#define Tv   12
#define Nv   1024
#define KSv  3
#define OUTv 64

#define Kdim   (KSv*Nv)        // 3072
#define Mrows  (Bv*Cv*Tv)      // 24576
#define BT     (Bv*Tv)         // 384

// ---------------- scratch ----------------
__device__ __half g_LkH[KSv * Nv * Nv];            // fp16(Lk), natural [k][n][m]
__device__ __half g_YH [(size_t)Mrows * Kdim];     // channel-mix output (fp16)
__device__ __half g_X1 [(size_t)Mrows * Nv];
__device__ __half g_X2 [(size_t)Mrows * Nv];
__device__ __half g_Th1[192 * 64];
__device__ __half g_Th2[192 * 64];
__device__ __half g_FcW[OUTv * Cv];                // fp16(fc_w) [j][o]

static __half *pLkH = nullptr, *pYH = nullptr;
static __half *pX1 = nullptr, *pX2 = nullptr, *pTh1 = nullptr, *pTh2 = nullptr;
static __half *pFcW = nullptr;

// ---- helpers ----
__device__ __forceinline__ void mma_f16(float& c0, float& c1, float& c2, float& c3,
                                        uint32_t a0, uint32_t a1, uint32_t a2, uint32_t a3,
                                        uint32_t b0, uint32_t b1) {
    asm volatile(
        "mma.sync.aligned.m16n8k16.row.col.f32.f16.f16.f32 "
        "{%0,%1,%2,%3}, {%4,%5,%6,%7}, {%8,%9}, {%0,%1,%2,%3};"
        : "+f"(c0), "+f"(c1), "+f"(c2), "+f"(c3)
        : "r"(a0), "r"(a1), "r"(a2), "r"(a3), "r"(b0), "r"(b1));
}

__device__ __forceinline__ void ldsm_x4(uint32_t& r0, uint32_t& r1, uint32_t& r2, uint32_t& r3,
                                        uint32_t addr) {
    asm volatile("ldmatrix.sync.aligned.m8n8.x4.shared.b16 {%0,%1,%2,%3}, [%4];"
                 : "=r"(r0), "=r"(r1), "=r"(r2), "=r"(r3) : "r"(addr));
}
__device__ __forceinline__ void ldsm_x4_t(uint32_t& r0, uint32_t& r1, uint32_t& r2, uint32_t& r3,
                                          uint32_t addr) {
    asm volatile("ldmatrix.sync.aligned.m8n8.x4.trans.shared.b16 {%0,%1,%2,%3}, [%4];"
                 : "=r"(r0), "=r"(r1), "=r"(r2), "=r"(r3) : "r"(addr));
}

__device__ __forceinline__ void cp16(uint32_t dst_smem, const void* src) {
    asm volatile("cp.async.cg.shared.global [%0], [%1], 16;" :: "r"(dst_smem), "l"(src));
}
__device__ __forceinline__ void cp_commit() { asm volatile("cp.async.commit_group;"); }

// ---------------- prep: Lk + thetas + fcw, ONE launch ----------------
__global__ __launch_bounds__(256) void prep_all(const float* __restrict__ Lk,
                                                const float* __restrict__ th1,
                                                const float* __restrict__ th2,
                                                const float* __restrict__ fcw,
                                                __half* __restrict__ LkH,
                                                __half* __restrict__ o1,
                                                __half* __restrict__ o2,
                                                __half* __restrict__ fcwH)
{
    int bid = blockIdx.x;
    if (bid < 3072) {
        size_t i = (size_t)bid * 1024 + threadIdx.x * 4;
        float4 v = *reinterpret_cast<const float4*>(Lk + i);
        *reinterpret_cast<__half2*>(LkH + i)     = __floats2half2_rn(v.x, v.y);
        *reinterpret_cast<__half2*>(LkH + i + 2) = __floats2half2_rn(v.z, v.w);
    } else if (bid < 3168) {
        int b2 = bid - 3072;                 // 0..95
        const float* src = (b2 >= 48) ? th2 : th1;
        __half*      dst = (b2 >= 48) ? o2  : o1;
        int idx = (b2 % 48) * 256 + threadIdx.x;
        int i = idx / 192;
        int p = idx - i * 192;
        dst[p * 64 + i] = __float2half_rn(src[idx]);
    } else {
        for (int i = threadIdx.x; i < OUTv * Cv; i += 256)
            fcwH[i] = __float2half_rn(fcw[i]);
    }
}

// ---------------- kernel B: channel mix, 2 m-blocks per CTA ----------------
#define CM_AROW 144
#define CM_BROW 272
#define CM_SMEM (192*CM_AROW + 2*64*CM_BROW)   // 27648 + 34816 = 62464 B

template <bool XF32>
__global__ __launch_bounds__(256, 2) void channel_mix_f16(const void* __restrict__ Xv,
                                                          const __half* __restrict__ thT,
                                                          __half* __restrict__ Y)
{
    extern __shared__ __half cmsm[];
    __half* As = cmsm;                                  // [192][72]
    __half* Bs = cmsm + 192 * (CM_AROW/2);              // [2][64][136]
    const uint32_t smA = (uint32_t)__cvta_generic_to_shared(As);
    const uint32_t smB = (uint32_t)__cvta_generic_to_shared(Bs);

    const int bt = blockIdx.x;
    const int b  = bt / Tv;
    const int t  = bt % Tv;
    const int mb0 = blockIdx.y * 2;       // first of two m-blocks
    const int tid  = threadIdx.x;
    const int wid  = tid >> 5;
    const int lane = tid & 31;
    const int gq = lane >> 2;
    const int tg = lane & 3;
    const int wm = (wid & 3) * 48;
    const int wn = (wid >> 2) * 64;

    // theta tile (once)
    #pragma unroll
    for (int l = 0; l < 6; l++) {
        int slot = tid + 256 * l;
        int p = slot >> 3, q = slot & 7;
        cp16(smA + (uint32_t)(p * CM_AROW + q * 16), thT + p * 64 + q * 8);
    }
    // both x tiles
    if (XF32) {
        const float* X = (const float*)Xv;
        #pragma unroll
        for (int mb = 0; mb < 2; mb++) {
            int m0 = (mb0 + mb) * 128;
            __half* Bsl = Bs + mb * 64 * (CM_BROW/2);
            #pragma unroll
            for (int l = 0; l < 8; l++) {
                int f  = tid + 256 * l;
                int i  = f >> 5;
                int mv = (f & 31) * 4;
                float4 v = *reinterpret_cast<const float4*>(
                    X + ((size_t)(b * Cv + i) * Tv + t) * Nv + m0 + mv);
                __half* dst = &Bsl[i * (CM_BROW/2) + mv];
                *reinterpret_cast<__half2*>(dst)     = __floats2half2_rn(v.x, v.y);
                *reinterpret_cast<__half2*>(dst + 2) = __floats2half2_rn(v.z, v.w);
            }
        }
    } else {
        const __half* X = (const __half*)Xv;
        #pragma unroll
        for (int mb = 0; mb < 2; mb++) {
            int m0 = (mb0 + mb) * 128;
            uint32_t Bsl = smB + mb * 64 * CM_BROW;
            #pragma unroll
            for (int l = 0; l < 4; l++) {
                int slot = tid + 256 * l;
                int i = slot >> 4, q = slot & 15;
                cp16(Bsl + (uint32_t)(i * CM_BROW + q * 16),
                     X + ((size_t)(b * Cv + i) * Tv + t) * Nv + m0 + q * 8);
            }
        }
    }
    cp_commit();
    asm volatile("cp.async.wait_group 0;" ::: "memory");
    __syncthreads();

    const int rowA = (lane & 7) + ((lane >> 3) & 1) * 8;
    const int colA = (lane >> 4) * 16;
    const int rowB = (lane & 7) + ((lane >> 3) & 1) * 8;
    const int colB = ((lane >> 4) & 1) * 16;

    for (int mb = 0; mb < 2; mb++) {
        const int m0 = (mb0 + mb) * 128;
        const uint32_t Bsl = smB + mb * 64 * CM_BROW;

        float acc[3][8][4];
        #pragma unroll
        for (int a = 0; a < 3; a++)
            #pragma unroll
            for (int c = 0; c < 8; c++)
                #pragma unroll
                for (int q = 0; q < 4; q++) acc[a][c][q] = 0.f;

        #pragma unroll
        for (int ks = 0; ks < 4; ks++) {
            uint32_t af[3][4];
            #pragma unroll
            for (int mt = 0; mt < 3; mt++)
                ldsm_x4(af[mt][0], af[mt][1], af[mt][2], af[mt][3],
                        smA + (uint32_t)((wm + 16*mt + rowA) * CM_AROW + ks * 32 + colA));
            uint32_t bf[8][2];
            #pragma unroll
            for (int ntp = 0; ntp < 4; ntp++)
                ldsm_x4_t(bf[2*ntp][0], bf[2*ntp][1], bf[2*ntp+1][0], bf[2*ntp+1][1],
                          Bsl + (uint32_t)((ks*16 + rowB) * CM_BROW + (wn + 16*ntp) * 2 + colB));
            #pragma unroll
            for (int mt = 0; mt < 3; mt++)
                #pragma unroll
                for (int nt = 0; nt < 8; nt++)
                    mma_f16(acc[mt][nt][0], acc[mt][nt][1], acc[mt][nt][2], acc[mt][nt][3],
                            af[mt][0], af[mt][1], af[mt][2], af[mt][3],
                            bf[nt][0], bf[nt][1]);
        }

        #pragma unroll
        for (int mt = 0; mt < 3; mt++) {
            int p1 = wm + 16 * mt + gq;
            int p2 = p1 + 8;
            int o1 = p1 / 3, k1 = p1 - o1 * 3;
            int o2 = p2 / 3, k2 = p2 - o2 * 3;
            size_t r1 = ((size_t)(b * Cv + o1) * Tv + t) * (size_t)Kdim + (size_t)k1 * Nv;
            size_t r2 = ((size_t)(b * Cv + o2) * Tv + t) * (size_t)Kdim + (size_t)k2 * Nv;
            #pragma unroll
            for (int nt = 0; nt < 8; nt++) {
                int c = m0 + wn + 8 * nt + 2 * tg;
                *reinterpret_cast<__half2*>(Y + r1 + c) = __floats2half2_rn(acc[mt][nt][0], acc[mt][nt][1]);
                *reinterpret_cast<__half2*>(Y + r2 + c) = __floats2half2_rn(acc[mt][nt][2], acc[mt][nt][3]);
            }
        }
    }
}

// ---------------- kernel C: fp16 mma GEMM, tile 96x128, GBK=64, NSTAGE=3 ----
#define GBM 96
#define GBK 64
#define AROW 144
#define STAGE_ROWS (GBM + 128)
#define STAGE_BYTES (STAGE_ROWS * AROW)
#define NSTAGE 3
#define GSMEM_BYTES (NSTAGE*STAGE_BYTES)

template <bool RF32>
__global__ __launch_bounds__(256, 2) void gemm_f16(const __half* __restrict__ A,
                                                   const __half* __restrict__ Bk,
                                                   const float*  __restrict__ bias,
                                                   const void*   __restrict__ residv,
                                                   __half*       __restrict__ Cout)
{
    extern __shared__ char smem[];
    const uint32_t sbase = (uint32_t)__cvta_generic_to_shared(smem);

    const int bn  = blockIdx.x;
    const int bm  = blockIdx.y;
    const int tid = threadIdx.x;
    const int wid = tid >> 5;
    const int lane = tid & 31;
    const int gq  = lane >> 2;
    const int tg  = lane & 3;
    const int wm  = (wid & 1) * 48;
    const int wn  = (wid >> 1) * 32;

    const __half* Abase = A + (size_t)bm * GBM * Kdim;
    const __half* Bbase = Bk + (size_t)bn * 128 * Nv;

    auto fill_stage = [&](int c) {
        int s = c % NSTAGE;
        const int k  = c >> 4;
        const int m0 = (c & 15) << 6;
        const __half* Asrc = Abase + (size_t)c * GBK;
        const __half* Bsrc = Bbase + ((size_t)k << 20) + m0;
        const uint32_t Asm = sbase + s * STAGE_BYTES;
        const uint32_t Bsm = Asm + GBM * AROW;
        #pragma unroll
        for (int l = 0; l < 7; l++) {
            int slot = tid + 256 * l;
            int row = slot >> 3, q = slot & 7;
            if (row < GBM)
                cp16(Asm + row * AROW + q * 16, Asrc + (size_t)row * Kdim + q * 8);
            else
                cp16(Bsm + (row - GBM) * AROW + q * 16, Bsrc + (size_t)(row - GBM) * Nv + q * 8);
        }
        cp_commit();
    };

    float acc[3][4][4];
    #pragma unroll
    for (int i = 0; i < 3; i++)
        #pragma unroll
        for (int j = 0; j < 4; j++)
            #pragma unroll
            for (int q = 0; q < 4; q++) acc[i][j][q] = 0.f;

    fill_stage(0);
    fill_stage(1);

    const int rowA = (lane & 7) + ((lane >> 3) & 1) * 8;
    const int colA = (lane >> 4) * 16;
    const int rowB = (lane & 7) + ((lane >> 4) & 1) * 8;
    const int colB = ((lane >> 3) & 1) * 16;

    const int NITER = Kdim / GBK;
    for (int it = 0; it < NITER; it++) {
        asm volatile("cp.async.wait_group 1;" ::: "memory");
        __syncthreads();

        if (it + 2 < NITER) fill_stage(it + 2);
        else                cp_commit();

        const uint32_t Acur = sbase + (it % NSTAGE) * STAGE_BYTES;
        const uint32_t Bcur = Acur + GBM * AROW;

        #pragma unroll
        for (int kh = 0; kh < 4; kh++) {
            const int kb = kh * 32;
            uint32_t af[3][4];
            #pragma unroll
            for (int mt = 0; mt < 3; mt++)
                ldsm_x4(af[mt][0], af[mt][1], af[mt][2], af[mt][3],
                        Acur + (uint32_t)((wm + 16*mt + rowA) * AROW + kb + colA));
            uint32_t bf[4][2];
            #pragma unroll
            for (int ntp = 0; ntp < 2; ntp++)
                ldsm_x4(bf[2*ntp][0], bf[2*ntp][1], bf[2*ntp+1][0], bf[2*ntp+1][1],
                        Bcur + (uint32_t)((wn + 16*ntp + rowB) * AROW + kb + colB));
            #pragma unroll
            for (int mt = 0; mt < 3; mt++)
                #pragma unroll
                for (int nt = 0; nt < 4; nt++)
                    mma_f16(acc[mt][nt][0], acc[mt][nt][1], acc[mt][nt][2], acc[mt][nt][3],
                            af[mt][0], af[mt][1], af[mt][2], af[mt][3],
                            bf[nt][0], bf[nt][1]);
        }
    }

    #pragma unroll
    for (int mt = 0; mt < 3; mt++) {
        int r1 = bm * GBM + wm + 16 * mt + gq;
        int r2 = r1 + 8;
        float bv1 = bias[(r1 / Tv) & (Cv - 1)];
        float bv2 = bias[(r2 / Tv) & (Cv - 1)];
        #pragma unroll
        for (int nt = 0; nt < 4; nt++) {
            int c = bn * 128 + wn + 8 * nt + 2 * tg;
            float z10, z11, z20, z21;
            if (RF32) {
                const float* rp = (const float*)residv;
                float2 a = *reinterpret_cast<const float2*>(rp + (size_t)r1 * Nv + c);
                float2 b2_ = *reinterpret_cast<const float2*>(rp + (size_t)r2 * Nv + c);
                z10 = a.x;  z11 = a.y;  z20 = b2_.x; z21 = b2_.y;
            } else {
                const __half* rp = (const __half*)residv;
                __half2 a = *reinterpret_cast<const __half2*>(rp + (size_t)r1 * Nv + c);
                __half2 b2_ = *reinterpret_cast<const __half2*>(rp + (size_t)r2 * Nv + c);
                z10 = __low2float(a);  z11 = __high2float(a);
                z20 = __low2float(b2_); z21 = __high2float(b2_);
            }
            float v0 = fmaxf(acc[mt][nt][0] + bv1 + z10, 0.f);
            float v1 = fmaxf(acc[mt][nt][1] + bv1 + z11, 0.f);
            float v2 = fmaxf(acc[mt][nt][2] + bv2 + z20, 0.f);
            float v3 = fmaxf(acc[mt][nt][3] + bv2 + z21, 0.f);
            *reinterpret_cast<__half2*>(Cout + (size_t)r1 * Nv + c) = __floats2half2_rn(v0, v1);
            *reinterpret_cast<__half2*>(Cout + (size_t)r2 * Nv + c) = __floats2half2_rn(v2, v3);
        }
    }
}

// ---------------- kernel D: final FC via fp16 mma ----------------
// out[(bt,n)][j] = sum_o X2[(b,o,t)][n] * fcwH[j][o] + fcb[j]
#define FC_WROW 144           // 64 halfs + 8 pad
#define FC_XROW 272           // 128 halfs + 8 pad

__global__ __launch_bounds__(256, 2) void fc_mma(const __half* __restrict__ X2c,
                                                 const __half* __restrict__ fcwH,
                                                 const float* __restrict__ fcb,
                                                 float*       __restrict__ out)
{
    __shared__ __half Ws[OUTv * (FC_WROW/2)];
    __shared__ __half Xs[Cv * (FC_XROW/2)];
    __shared__ float  bsf[OUTv];
    const uint32_t smW = (uint32_t)__cvta_generic_to_shared(Ws);
    const uint32_t smX = (uint32_t)__cvta_generic_to_shared(Xs);

    const int bt = blockIdx.x;
    const int b  = bt / Tv;
    const int t  = bt % Tv;
    const int n0 = blockIdx.y * 128;
    const int tid  = threadIdx.x;
    const int wid  = tid >> 5;
    const int lane = tid & 31;
    const int gq = lane >> 2;
    const int tg = lane & 3;
    const int wm = (wid & 3) * 32;     // n (output row) dim
    const int wn = (wid >> 2) * 32;    // j (output col) dim

    // W tile: 64 rows x 128B -> 512 cp16 (2/thread)
    #pragma unroll
    for (int l = 0; l < 2; l++) {
        int slot = tid + 256 * l;
        int j = slot >> 3, q = slot & 7;
        cp16(smW + (uint32_t)(j * FC_WROW + q * 16), fcwH + j * Cv + q * 8);
    }
    // X tile: 64 rows x 256B -> 1024 cp16 (4/thread)
    #pragma unroll
    for (int l = 0; l < 4; l++) {
        int slot = tid + 256 * l;
        int o = slot >> 4, q = slot & 15;
        cp16(smX + (uint32_t)(o * FC_XROW + q * 16),
             X2c + ((size_t)(b * Cv + o) * Tv + t) * Nv + n0 + q * 8);
    }
    if (tid < OUTv) bsf[tid] = fcb[tid];
    cp_commit();
    asm volatile("cp.async.wait_group 0;" ::: "memory");
    __syncthreads();

    float acc[2][4][4];
    #pragma unroll
    for (int i = 0; i < 2; i++)
        #pragma unroll
        for (int j = 0; j < 4; j++)
            #pragma unroll
            for (int q = 0; q < 4; q++) acc[i][j][q] = 0.f;

    // A (trans from [o][n] tile): bit4 -> k+8 row, bit3 -> m+8 col
    const int rowAt = (lane & 7) + ((lane >> 4) & 1) * 8;
    const int colAt = ((lane >> 3) & 1) * 16;
    // B (non-trans from [j][o] tile): bit4 -> n+8 row, bit3 -> k+8 col
    const int rowB = (lane & 7) + ((lane >> 4) & 1) * 8;
    const int colB = ((lane >> 3) & 1) * 16;

    #pragma unroll
    for (int ks = 0; ks < 4; ks++) {
        uint32_t af[2][4];
        #pragma unroll
        for (int mt = 0; mt < 2; mt++)
            ldsm_x4_t(af[mt][0], af[mt][1], af[mt][2], af[mt][3],
                      smX + (uint32_t)((ks*16 + rowAt) * FC_XROW + (wm + 16*mt) * 2 + colAt));
        uint32_t bf[4][2];
        #pragma unroll
        for (int ntp = 0; ntp < 2; ntp++)
            ldsm_x4(bf[2*ntp][0], bf[2*ntp][1], bf[2*ntp+1][0], bf[2*ntp+1][1],
                    smW + (uint32_t)((wn + 16*ntp + rowB) * FC_WROW + ks * 32 + colB));
        #pragma unroll
        for (int mt = 0; mt < 2; mt++)
            #pragma unroll
            for (int nt = 0; nt < 4; nt++)
                mma_f16(acc[mt][nt][0], acc[mt][nt][1], acc[mt][nt][2], acc[mt][nt][3],
                        af[mt][0], af[mt][1], af[mt][2], af[mt][3],
                        bf[nt][0], bf[nt][1]);
    }

    // epilogue: + fcb, fp32 out, coalesced float2
    #pragma unroll
    for (int mt = 0; mt < 2; mt++) {
        int nr1 = wm + 16 * mt + gq;
        int nr2 = nr1 + 8;
        size_t o1 = ((size_t)bt * Nv + n0 + nr1) * OUTv;
        size_t o2 = ((size_t)bt * Nv + n0 + nr2) * OUTv;
        #pragma unroll
        for (int nt = 0; nt < 4; nt++) {
            int j = wn + 8 * nt + 2 * tg;
            float bj0 = bsf[j], bj1 = bsf[j + 1];
            float2 v1 = make_float2(acc[mt][nt][0] + bj0, acc[mt][nt][1] + bj1);
            float2 v2 = make_float2(acc[mt][nt][2] + bj0, acc[mt][nt][3] + bj1);
            *reinterpret_cast<float2*>(out + o1 + j) = v1;
            *reinterpret_cast<float2*>(out + o2 + j) = v2;
        }
    }
}

// ---------------- static-init module materialization ----------------
namespace {
struct ModuleLoader {
    ModuleLoader() {
        cudaFree(0);
        cudaGetSymbolAddress((void**)&pLkH, g_LkH);
        cudaGetSymbolAddress((void**)&pYH,  g_YH);
        cudaGetSymbolAddress((void**)&pX1,  g_X1);
        cudaGetSymbolAddress((void**)&pX2,  g_X2);
        cudaGetSymbolAddress((void**)&pTh1, g_Th1);
        cudaGetSymbolAddress((void**)&pTh2, g_Th2);
        cudaGetSymbolAddress((void**)&pFcW, g_FcW);
        cudaMemset(pLkH, 0, 4);
        cudaMemset(pYH,  0, 4);
        cudaMemset(pX1,  0, 4);
        cudaMemset(pX2,  0, 4);
        cudaMemset(pTh1, 0, 4);
        cudaMemset(pTh2, 0, 4);
        cudaMemset(pFcW, 0, 4);
        cudaFuncSetAttribute(gemm_f16<true>,  cudaFuncAttributeMaxDynamicSharedMemorySize, GSMEM_BYTES);
        cudaFuncSetAttribute(gemm_f16<false>, cudaFuncAttributeMaxDynamicSharedMemorySize, GSMEM_BYTES);
        cudaFuncSetAttribute(channel_mix_f16<true>,  cudaFuncAttributeMaxDynamicSharedMemorySize, CM_SMEM);
        cudaFuncSetAttribute(channel_mix_f16<false>, cudaFuncAttributeMaxDynamicSharedMemorySize, CM_SMEM);
        cudaDeviceSynchronize();
    }
};
ModuleLoader g_loader;
}

// ---------------- launch ----------------
extern "C" void kernel_launch(void* const* d_in, const int* in_sizes, int n_in,
                              void* d_out, int out_size)
{
    const float* x      = (const float*)d_in[0];
    const float* Lk     = (const float*)d_in[1];
    const float* theta1 = (const float*)d_in[2];
    const float* b1     = (const float*)d_in[3];
    const float* theta2 = (const float*)d_in[4];
    const float* b2     = (const float*)d_in[5];
    const float* fc_w   = (const float*)d_in[6];
    const float* fc_b   = (const float*)d_in[7];
    float* out = (float*)d_out;

    // 1) prep: Lk + thetas + fcw, one launch
    prep_all<<<3072 + 96 + 1, 256>>>(Lk, theta1, theta2, fc_w, pLkH, pTh1, pTh2, pFcW);

    // 2) layer 1
    channel_mix_f16<true><<<dim3(BT, Nv / 256), 256, CM_SMEM>>>(x, pTh1, pYH);
    gemm_f16<true><<<dim3(8, Mrows / GBM), 256, GSMEM_BYTES>>>(pYH, pLkH, b1, x, pX1);

    // 3) layer 2
    channel_mix_f16<false><<<dim3(BT, Nv / 256), 256, CM_SMEM>>>(pX1, pTh2, pYH);
    gemm_f16<false><<<dim3(8, Mrows / GBM), 256, GSMEM_BYTES>>>(pYH, pLkH, b2, pX1, pX2);

    // 4) final FC (fp16 mma)
    fc_mma<<<dim3(BT, Nv / 128), 256>>>(pX2, pFcW, fc_b, out);
}